// round 14
// baseline (speedup 1.0000x reference)
#include <cuda_runtime.h>
#include <math.h>

#define BS 32
#define NF 33
#define KDIM 4096
#define SATN (32*64*64*64)
#define NKC 8            // k-chunk blocks per freq in fgemm
#define NKC2 32          // Cp partial slots (NKC * 4 k-subsets)

// -------- device scratch --------
__device__ float2 g_Sh[(size_t)NF * BS * KDIM];
__device__ float2 g_Gh[(size_t)NF * BS * KDIM];
__device__ float2 g_Sw[(size_t)NF * BS * KDIM];
__device__ float2 g_Gw[(size_t)NF * BS * KDIM];
__device__ float2 g_CpH[NKC2 * NF * BS * BS];
__device__ float2 g_CpW[NKC2 * NF * BS * BS];
__device__ float  g_normp[2048];

// cos(k*pi/32), k = 0..63. sin(k*pi/32) = TWC[(k+48)&63].
// All accesses use compile-time indices -> values fold into FFMA immediates.
__device__ constexpr float TWC[64] = {
     1.0f,
     0.9951847266721969f,  0.9807852804032304f,  0.9569403357322088f,
     0.9238795325112868f,  0.8819212643483551f,  0.8314696123025452f,
     0.7730104533627370f,  0.7071067811865476f,  0.6343932841636455f,
     0.5555702330196022f,  0.4713967368259976f,  0.3826834323650898f,
     0.2902846772544623f,  0.1950903220161283f,  0.0980171403295606f,
     0.0f,
    -0.0980171403295606f, -0.1950903220161283f, -0.2902846772544623f,
    -0.3826834323650898f, -0.4713967368259976f, -0.5555702330196022f,
    -0.6343932841636455f, -0.7071067811865476f, -0.7730104533627370f,
    -0.8314696123025452f, -0.8819212643483551f, -0.9238795325112868f,
    -0.9569403357322088f, -0.9807852804032304f, -0.9951847266721969f,
    -1.0f,
    -0.9951847266721969f, -0.9807852804032304f, -0.9569403357322088f,
    -0.9238795325112868f, -0.8819212643483551f, -0.8314696123025452f,
    -0.7730104533627370f, -0.7071067811865476f, -0.6343932841636455f,
    -0.5555702330196022f, -0.4713967368259976f, -0.3826834323650898f,
    -0.2902846772544623f, -0.1950903220161283f, -0.0980171403295606f,
     0.0f,
     0.0980171403295606f,  0.1950903220161283f,  0.2902846772544623f,
     0.3826834323650898f,  0.4713967368259976f,  0.5555702330196022f,
     0.6343932841636455f,  0.7071067811865476f,  0.7730104533627370f,
     0.8314696123025452f,  0.8819212643483551f,  0.9238795325112868f,
     0.9569403357322088f,  0.9807852804032304f,  0.9951847266721969f
};

// -------- DFT build: seo[n*65+col] = (e[n], o[n]); seo[32*65+col].x = e32 --------
__device__ __forceinline__ void dft_build(
    const float* slab, float2* seo, int axisH, int cc, int col, int m)
{
#pragma unroll
    for (int nn = 0; nn < 8; nn++) {
        int n = m + 4 * nn;
        float a, bb;
        if (axisH) {
            a  = slab[n * 65 + cc];
            bb = n ? slab[(64 - n) * 65 + cc] : 0.f;
        } else {
            a  = slab[cc * 65 + n];
            bb = n ? slab[cc * 65 + (64 - n)] : 0.f;
        }
        seo[n * 65 + col] = make_float2(a + bb, a - bb);
    }
    if (m == 0)
        seo[32 * 65 + col] =
            make_float2(axisH ? slab[32 * 65 + cc] : slab[cc * 65 + 32], 0.f);
}

// Compile-time-M DFT (R12-proven): thread handles f = M, M+4, ..., M+28 (+ f=32 for M=0).
template<int M>
__device__ __noinline__ void dft_compute_t(
    const float2* seo, float2* __restrict__ dst, int i, size_t off, int col)
{
    float e0  = seo[col].x;
    float e32 = seo[32 * 65 + col].x;
    float base = (M & 1) ? (e0 - e32) : (e0 + e32);

    float ar[8], ai[8];
#pragma unroll
    for (int u = 0; u < 8; u++) { ar[u] = base; ai[u] = 0.f; }

#pragma unroll
    for (int n = 1; n < 32; n++) {
        float2 eo = seo[n * 65 + col];
#pragma unroll
        for (int u = 0; u < 8; u++) {
            const int k = (((M + 4 * u) * n) & 63);        // compile-time
            ar[u] = fmaf(eo.x, TWC[k], ar[u]);
            ai[u] = fmaf(eo.y, TWC[(k + 48) & 63], ai[u]);
        }
    }
#pragma unroll
    for (int u = 0; u < 8; u++) {
        int f1 = M + 4 * u;
        dst[((size_t)f1 * BS + i) * KDIM + off] = make_float2(ar[u], -ai[u]);
    }
    if (M == 0) {                          // f = 32: cos = (-1)^n, sin = 0
        float arx = e0 + e32;
#pragma unroll
        for (int n = 1; n < 32; n++)
            arx = fmaf(seo[n * 65 + col].x, (n & 1) ? -1.f : 1.f, arx);
        dst[((size_t)32 * BS + i) * KDIM + off] = make_float2(arx, 0.f);
    }
}

__device__ __forceinline__ void dft_compute(
    const float2* seo, float2* __restrict__ dst, int i, size_t off, int col, int m)
{
    switch (m) {                           // warp-uniform branch
        case 0: dft_compute_t<0>(seo, dst, i, off, col); break;
        case 1: dft_compute_t<1>(seo, dst, i, off, col); break;
        case 2: dft_compute_t<2>(seo, dst, i, off, col); break;
        default: dft_compute_t<3>(seo, dst, i, off, col); break;
    }
}

// -------- merged DFT: sat+grd, H+W axes, passthrough copy, norm (R12-proven) --------
__global__ void __launch_bounds__(256, 4)
k_dft3(const float* __restrict__ sat, const float* __restrict__ grd,
       float* __restrict__ out)
{
    __shared__ float slab[64 * 65];
    __shared__ __align__(16) float2 seo[33 * 65];
    __shared__ float red[8];

    int b = blockIdx.x;
    int tid = threadIdx.x;
    int is_grd = (b >= 2048);
    int b2 = is_grd ? (b - 2048) : b;
    const float* p = (is_grd ? grd : sat) + (size_t)b2 * 4096;
    float* op = out + (is_grd ? (size_t)SATN : 0) + (size_t)b2 * 4096;

    float nacc = 0.f;
#pragma unroll
    for (int t = 0; t < 16; t++) {
        int idx = tid + t * 256;
        float v = p[idx];
        slab[(idx >> 6) * 65 + (idx & 63)] = v;
        op[idx] = v;
        nacc = fmaf(v, v, nacc);
    }

    if (!is_grd) {
#pragma unroll
        for (int o = 16; o > 0; o >>= 1)
            nacc += __shfl_down_sync(0xffffffffu, nacc, o);
        if ((tid & 31) == 0) red[tid >> 5] = nacc;
    }
    __syncthreads();
    if (!is_grd && tid == 0) {
        float s = 0.f;
#pragma unroll
        for (int w = 0; w < 8; w++) s += red[w];
        g_normp[b2] = s;
    }

    int col = tid & 63;
    int m   = tid >> 6;
    int i = b2 >> 6, c = b2 & 63;
    size_t off = (size_t)c * 64 + col;

    {
        int cc = is_grd ? (63 - col) : col;
        dft_build(slab, seo, 1, cc, col, m);
        __syncthreads();
        dft_compute(seo, is_grd ? g_Gh : g_Sh, i, off, col, m);
    }
    __syncthreads();
    {
        dft_build(slab, seo, 0, col, col, m);
        __syncthreads();
        dft_compute(seo, is_grd ? g_Gw : g_Sw, i, off, col, m);
    }
}

// -------- per-frequency complex GEMM, 3-mult (Karatsuba) MACs, 4x4 tiles --------
// ONLY change vs R12: launch_bounds 2 -> 3 blocks/SM.
#define FST 36
__global__ void __launch_bounds__(256, 3) k_fgemm3() {
    __shared__ __align__(16) float sSr[32 * FST];
    __shared__ __align__(16) float sSi[32 * FST];
    __shared__ __align__(16) float sSp[32 * FST];
    __shared__ __align__(16) float sG1[32 * FST];
    __shared__ __align__(16) float sG2[32 * FST];
    __shared__ __align__(16) float sG3[32 * FST];

    int bid = blockIdx.x;
    int sel = (bid >= NF * NKC);
    if (sel) bid -= NF * NKC;
    int f  = bid >> 3;
    int kc = bid & 7;

    const float2* S = sel ? g_Sw : g_Sh;
    const float2* G = sel ? g_Gw : g_Gh;
    float2* Cp      = sel ? g_CpW : g_CpH;

    int tid = threadIdx.x;
    int li = tid >> 3;
    int ls = tid & 7;
    int t    = tid & 63;
    int ksub = tid >> 6;
    int i0 = (t >> 3) * 4;
    int j0 = (t & 7) * 4;

    const float2* Sb = S + (size_t)f * BS * KDIM + kc * 512;
    const float2* Gb = G + (size_t)f * BS * KDIM + kc * 512;
    const float4* Sg4 = (const float4*)(Sb + (size_t)li * KDIM);
    const float4* Gg4 = (const float4*)(Gb + (size_t)li * KDIM);

    float K1[4][4], K2[4][4], K3[4][4];
#pragma unroll
    for (int di = 0; di < 4; di++)
#pragma unroll
        for (int dj = 0; dj < 4; dj++) { K1[di][dj] = 0.f; K2[di][dj] = 0.f; K3[di][dj] = 0.f; }

    for (int kt = 0; kt < 16; kt++) {
        __syncthreads();
#pragma unroll
        for (int u = 0; u < 2; u++) {
            int k4 = ls + u * 8;
            float4 s = Sg4[kt * 16 + k4];
            float4 g = Gg4[kt * 16 + k4];
            int r0 = (2 * k4) * FST + li, r1 = (2 * k4 + 1) * FST + li;
            sSr[r0] = s.x;  sSi[r0] = s.y;  sSp[r0] = s.x + s.y;
            sSr[r1] = s.z;  sSi[r1] = s.w;  sSp[r1] = s.z + s.w;
            sG1[r0] = g.x;  sG2[r0] = -g.y - g.x;  sG3[r0] = g.x - g.y;
            sG1[r1] = g.z;  sG2[r1] = -g.w - g.z;  sG3[r1] = g.z - g.w;
        }
        __syncthreads();
#pragma unroll
        for (int kk = 0; kk < 8; kk++) {
            int k = ksub * 8 + kk;
            float4 var = *(const float4*)&sSr[k * FST + i0];
            float4 vai = *(const float4*)&sSi[k * FST + i0];
            float4 vap = *(const float4*)&sSp[k * FST + i0];
            float4 vg1 = *(const float4*)&sG1[k * FST + j0];
            float4 vg2 = *(const float4*)&sG2[k * FST + j0];
            float4 vg3 = *(const float4*)&sG3[k * FST + j0];
            const float* par = (const float*)&var;
            const float* pai = (const float*)&vai;
            const float* pap = (const float*)&vap;
            const float* pg1 = (const float*)&vg1;
            const float* pg2 = (const float*)&vg2;
            const float* pg3 = (const float*)&vg3;
#pragma unroll
            for (int di = 0; di < 4; di++) {
#pragma unroll
                for (int dj = 0; dj < 4; dj++) {
                    K1[di][dj] = fmaf(pg1[dj], pap[di], K1[di][dj]);
                    K2[di][dj] = fmaf(pg2[dj], par[di], K2[di][dj]);
                    K3[di][dj] = fmaf(pg3[dj], pai[di], K3[di][dj]);
                }
            }
        }
    }
    int kc2 = kc * 4 + ksub;
    float2* outp = Cp + ((size_t)kc2 * NF + f) * BS * BS;
#pragma unroll
    for (int di = 0; di < 4; di++)
#pragma unroll
        for (int dj = 0; dj < 4; dj++)
            outp[(i0 + di) * 32 + (j0 + dj)] =
                make_float2(K1[di][dj] - K3[di][dj], K1[di][dj] + K2[di][dj]);
}

// -------- fused inverse transform + norm + first-max argmax + distance --------
__global__ void k_inv(float* __restrict__ out_dist, float* __restrict__ out_orien_f) {
    __shared__ float2 CH[4][NF], CW[4][NF];
    __shared__ float valsH[4][64], valsW[4][64];
    __shared__ float nred[4][2];
    int tid = threadIdx.x;
    int p = tid >> 6;
    int s = tid & 63;
    int pair = blockIdx.x * 4 + p;
    int i = pair >> 5, j = pair & 31;

    float nv = g_normp[i * 64 + s];
#pragma unroll
    for (int o = 16; o > 0; o >>= 1) nv += __shfl_down_sync(0xffffffffu, nv, o);
    if ((s & 31) == 0) nred[p][s >> 5] = nv;

    if (s < NF) {
        float xr = 0, xi = 0, yr = 0, yi = 0;
#pragma unroll
        for (int kc = 0; kc < NKC2; kc++) {
            float2 a = g_CpH[((kc * NF + s) * BS + i) * BS + j];
            float2 b = g_CpW[((kc * NF + s) * BS + i) * BS + j];
            xr += a.x; xi += a.y; yr += b.x; yi += b.y;
        }
        CH[p][s] = make_float2(xr, xi);
        CW[p][s] = make_float2(yr, yi);
    }
    __syncthreads();

    float sgn = (s & 1) ? -1.f : 1.f;
    float accH = CH[p][0].x + sgn * CH[p][32].x;
    float accW = CW[p][0].x + sgn * CW[p][32].x;
#pragma unroll
    for (int f = 1; f < 32; f++) {
        float x = (float)((f * s) & 63) / 32.0f;
        float sn, cs;
        sincospif(x, &sn, &cs);
        accH += 2.f * (CH[p][f].x * cs - CH[p][f].y * sn);
        accW += 2.f * (CW[p][f].x * cs - CW[p][f].y * sn);
    }
    valsH[p][s] = accH;
    valsW[p][s] = accW;
    __syncthreads();

    if (s == 0) {
        float best = valsH[p][0]; int bi = 0;
        for (int t = 1; t < 64; t++)
            if (valsH[p][t] > best) { best = valsH[p][t]; bi = t; }   // first max
        out_orien_f[i * 32 + j] = (float)bi;
        float nrm = sqrtf(nred[p][0] + nred[p][1] + 1e-8f);
        float q = valsW[p][bi] * (1.f / 64.f);
        float dot = q / nrm;
        out_dist[j * 32 + i] = 2.f - 2.f * dot;
    }
}

extern "C" void kernel_launch(void* const* d_in, const int* in_sizes, int n_in,
                              void* d_out, int out_size) {
    (void)in_sizes; (void)n_in; (void)out_size;
    const float* sat = (const float*)d_in[0];
    const float* grd = (const float*)d_in[1];
    float* out = (float*)d_out;

    k_dft3<<<4096, 256>>>(sat, grd, out);

    k_fgemm3<<<2 * NF * NKC, 256>>>();

    float* out_dist  = out + (size_t)2 * SATN;
    float* out_orien = out + (size_t)2 * SATN + 1024;
    k_inv<<<256, 256>>>(out_dist, out_orien);
}

// round 15
// speedup vs baseline: 1.5510x; 1.5510x over previous
#include <cuda_runtime.h>
#include <math.h>

#define BS 32
#define NF 33
#define KDIM 4096
#define SATN (32*64*64*64)
#define NKC 8            // k-chunk blocks per freq in fgemm
#define NKC2 32          // Cp partial slots (NKC * 4 k-subsets)

// -------- device scratch --------
__device__ float2 g_Sh[(size_t)NF * BS * KDIM];
__device__ float2 g_Gh[(size_t)NF * BS * KDIM];
__device__ float2 g_Sw[(size_t)NF * BS * KDIM];
__device__ float2 g_Gw[(size_t)NF * BS * KDIM];
__device__ float2 g_CpH[NKC2 * NF * BS * BS];
__device__ float2 g_CpW[NKC2 * NF * BS * BS];
__device__ float  g_normp[2048];

// cos(k*pi/32), k = 0..63. sin(k*pi/32) = TWC[(k+48)&63].
// All twiddle accesses use compile-time indices -> values fold into FFMA immediates.
__device__ constexpr float TWC[64] = {
     1.0f,
     0.9951847266721969f,  0.9807852804032304f,  0.9569403357322088f,
     0.9238795325112868f,  0.8819212643483551f,  0.8314696123025452f,
     0.7730104533627370f,  0.7071067811865476f,  0.6343932841636455f,
     0.5555702330196022f,  0.4713967368259976f,  0.3826834323650898f,
     0.2902846772544623f,  0.1950903220161283f,  0.0980171403295606f,
     0.0f,
    -0.0980171403295606f, -0.1950903220161283f, -0.2902846772544623f,
    -0.3826834323650898f, -0.4713967368259976f, -0.5555702330196022f,
    -0.6343932841636455f, -0.7071067811865476f, -0.7730104533627370f,
    -0.8314696123025452f, -0.8819212643483551f, -0.9238795325112868f,
    -0.9569403357322088f, -0.9807852804032304f, -0.9951847266721969f,
    -1.0f,
    -0.9951847266721969f, -0.9807852804032304f, -0.9569403357322088f,
    -0.9238795325112868f, -0.8819212643483551f, -0.8314696123025452f,
    -0.7730104533627370f, -0.7071067811865476f, -0.6343932841636455f,
    -0.5555702330196022f, -0.4713967368259976f, -0.3826834323650898f,
    -0.2902846772544623f, -0.1950903220161283f, -0.0980171403295606f,
     0.0f,
     0.0980171403295606f,  0.1950903220161283f,  0.2902846772544623f,
     0.3826834323650898f,  0.4713967368259976f,  0.5555702330196022f,
     0.6343932841636455f,  0.7071067811865476f,  0.7730104533627370f,
     0.8314696123025452f,  0.8819212643483551f,  0.9238795325112868f,
     0.9569403357322088f,  0.9807852804032304f,  0.9951847266721969f
};

// -------- DFT build: seo[n*65+col] = (e[n], o[n]); seo[32*65+col].x = e32 --------
__device__ __forceinline__ void dft_build(
    const float* slab, float2* seo, int axisH, int cc, int col, int m)
{
#pragma unroll
    for (int nn = 0; nn < 8; nn++) {
        int n = m + 4 * nn;
        float a, bb;
        if (axisH) {
            a  = slab[n * 65 + cc];
            bb = n ? slab[(64 - n) * 65 + cc] : 0.f;
        } else {
            a  = slab[cc * 65 + n];
            bb = n ? slab[cc * 65 + (64 - n)] : 0.f;
        }
        seo[n * 65 + col] = make_float2(a + bb, a - bb);
    }
    if (m == 0)
        seo[32 * 65 + col] =
            make_float2(axisH ? slab[32 * 65 + cc] : slab[cc * 65 + 32], 0.f);
}

// Compile-time-M DFT: thread handles f = M, M+4, ..., M+28 (+ f=32 for M=0).
template<int M>
__device__ __noinline__ void dft_compute_t(
    const float2* seo, float2* __restrict__ dst, int i, size_t off, int col)
{
    float e0  = seo[col].x;
    float e32 = seo[32 * 65 + col].x;
    float base = (M & 1) ? (e0 - e32) : (e0 + e32);

    float ar[8], ai[8];
#pragma unroll
    for (int u = 0; u < 8; u++) { ar[u] = base; ai[u] = 0.f; }

#pragma unroll
    for (int n = 1; n < 32; n++) {
        float2 eo = seo[n * 65 + col];
#pragma unroll
        for (int u = 0; u < 8; u++) {
            const int k = (((M + 4 * u) * n) & 63);        // compile-time
            ar[u] = fmaf(eo.x, TWC[k], ar[u]);
            ai[u] = fmaf(eo.y, TWC[(k + 48) & 63], ai[u]);
        }
    }
#pragma unroll
    for (int u = 0; u < 8; u++) {
        int f1 = M + 4 * u;
        dst[((size_t)f1 * BS + i) * KDIM + off] = make_float2(ar[u], -ai[u]);
    }
    if (M == 0) {                          // f = 32: cos = (-1)^n, sin = 0
        float arx = e0 + e32;
#pragma unroll
        for (int n = 1; n < 32; n++)
            arx = fmaf(seo[n * 65 + col].x, (n & 1) ? -1.f : 1.f, arx);
        dst[((size_t)32 * BS + i) * KDIM + off] = make_float2(arx, 0.f);
    }
}

__device__ __forceinline__ void dft_compute(
    const float2* seo, float2* __restrict__ dst, int i, size_t off, int col, int m)
{
    switch (m) {                           // warp-uniform branch
        case 0: dft_compute_t<0>(seo, dst, i, off, col); break;
        case 1: dft_compute_t<1>(seo, dst, i, off, col); break;
        case 2: dft_compute_t<2>(seo, dst, i, off, col); break;
        default: dft_compute_t<3>(seo, dst, i, off, col); break;
    }
}

// -------- merged DFT: sat+grd, H+W axes, passthrough copy, norm --------
__global__ void __launch_bounds__(256, 4)
k_dft3(const float* __restrict__ sat, const float* __restrict__ grd,
       float* __restrict__ out)
{
    __shared__ float slab[64 * 65];
    __shared__ __align__(16) float2 seo[33 * 65];
    __shared__ float red[8];

    int b = blockIdx.x;
    int tid = threadIdx.x;
    int is_grd = (b >= 2048);
    int b2 = is_grd ? (b - 2048) : b;
    const float* p = (is_grd ? grd : sat) + (size_t)b2 * 4096;
    float* op = out + (is_grd ? (size_t)SATN : 0) + (size_t)b2 * 4096;

    float nacc = 0.f;
#pragma unroll
    for (int t = 0; t < 16; t++) {
        int idx = tid + t * 256;
        float v = p[idx];
        slab[(idx >> 6) * 65 + (idx & 63)] = v;
        op[idx] = v;
        nacc = fmaf(v, v, nacc);
    }

    if (!is_grd) {
#pragma unroll
        for (int o = 16; o > 0; o >>= 1)
            nacc += __shfl_down_sync(0xffffffffu, nacc, o);
        if ((tid & 31) == 0) red[tid >> 5] = nacc;
    }
    __syncthreads();
    if (!is_grd && tid == 0) {
        float s = 0.f;
#pragma unroll
        for (int w = 0; w < 8; w++) s += red[w];
        g_normp[b2] = s;
    }

    int col = tid & 63;
    int m   = tid >> 6;
    int i = b2 >> 6, c = b2 & 63;
    size_t off = (size_t)c * 64 + col;

    {
        int cc = is_grd ? (63 - col) : col;
        dft_build(slab, seo, 1, cc, col, m);
        __syncthreads();
        dft_compute(seo, is_grd ? g_Gh : g_Sh, i, off, col, m);
    }
    __syncthreads();
    {
        dft_build(slab, seo, 0, col, col, m);
        __syncthreads();
        dft_compute(seo, is_grd ? g_Gw : g_Sw, i, off, col, m);
    }
}

// -------- per-frequency complex GEMM, 3-mult (Karatsuba) MACs, 4x4 tiles --------
#define FST 36
__global__ void __launch_bounds__(256, 2) k_fgemm3() {
    __shared__ __align__(16) float sSr[32 * FST];
    __shared__ __align__(16) float sSi[32 * FST];
    __shared__ __align__(16) float sSp[32 * FST];
    __shared__ __align__(16) float sG1[32 * FST];
    __shared__ __align__(16) float sG2[32 * FST];
    __shared__ __align__(16) float sG3[32 * FST];

    int bid = blockIdx.x;
    int sel = (bid >= NF * NKC);
    if (sel) bid -= NF * NKC;
    int f  = bid >> 3;
    int kc = bid & 7;

    const float2* S = sel ? g_Sw : g_Sh;
    const float2* G = sel ? g_Gw : g_Gh;
    float2* Cp      = sel ? g_CpW : g_CpH;

    int tid = threadIdx.x;
    int li = tid >> 3;
    int ls = tid & 7;
    int t    = tid & 63;
    int ksub = tid >> 6;
    int i0 = (t >> 3) * 4;
    int j0 = (t & 7) * 4;

    const float2* Sb = S + (size_t)f * BS * KDIM + kc * 512;
    const float2* Gb = G + (size_t)f * BS * KDIM + kc * 512;
    const float4* Sg4 = (const float4*)(Sb + (size_t)li * KDIM);
    const float4* Gg4 = (const float4*)(Gb + (size_t)li * KDIM);

    float K1[4][4], K2[4][4], K3[4][4];
#pragma unroll
    for (int di = 0; di < 4; di++)
#pragma unroll
        for (int dj = 0; dj < 4; dj++) { K1[di][dj] = 0.f; K2[di][dj] = 0.f; K3[di][dj] = 0.f; }

    for (int kt = 0; kt < 16; kt++) {
        __syncthreads();
#pragma unroll
        for (int u = 0; u < 2; u++) {
            int k4 = ls + u * 8;
            float4 s = Sg4[kt * 16 + k4];
            float4 g = Gg4[kt * 16 + k4];
            int r0 = (2 * k4) * FST + li, r1 = (2 * k4 + 1) * FST + li;
            sSr[r0] = s.x;  sSi[r0] = s.y;  sSp[r0] = s.x + s.y;
            sSr[r1] = s.z;  sSi[r1] = s.w;  sSp[r1] = s.z + s.w;
            sG1[r0] = g.x;  sG2[r0] = -g.y - g.x;  sG3[r0] = g.x - g.y;
            sG1[r1] = g.z;  sG2[r1] = -g.w - g.z;  sG3[r1] = g.z - g.w;
        }
        __syncthreads();
#pragma unroll
        for (int kk = 0; kk < 8; kk++) {
            int k = ksub * 8 + kk;
            float4 var = *(const float4*)&sSr[k * FST + i0];
            float4 vai = *(const float4*)&sSi[k * FST + i0];
            float4 vap = *(const float4*)&sSp[k * FST + i0];
            float4 vg1 = *(const float4*)&sG1[k * FST + j0];
            float4 vg2 = *(const float4*)&sG2[k * FST + j0];
            float4 vg3 = *(const float4*)&sG3[k * FST + j0];
            const float* par = (const float*)&var;
            const float* pai = (const float*)&vai;
            const float* pap = (const float*)&vap;
            const float* pg1 = (const float*)&vg1;
            const float* pg2 = (const float*)&vg2;
            const float* pg3 = (const float*)&vg3;
#pragma unroll
            for (int di = 0; di < 4; di++) {
#pragma unroll
                for (int dj = 0; dj < 4; dj++) {
                    K1[di][dj] = fmaf(pg1[dj], pap[di], K1[di][dj]);
                    K2[di][dj] = fmaf(pg2[dj], par[di], K2[di][dj]);
                    K3[di][dj] = fmaf(pg3[dj], pai[di], K3[di][dj]);
                }
            }
        }
    }
    int kc2 = kc * 4 + ksub;
    float2* outp = Cp + ((size_t)kc2 * NF + f) * BS * BS;
#pragma unroll
    for (int di = 0; di < 4; di++)
#pragma unroll
        for (int dj = 0; dj < 4; dj++)
            outp[(i0 + di) * 32 + (j0 + dj)] =
                make_float2(K1[di][dj] - K3[di][dj], K1[di][dj] + K2[di][dj]);
}

// -------- fused inverse transform + norm + first-max argmax + distance --------
__global__ void k_inv(float* __restrict__ out_dist, float* __restrict__ out_orien_f) {
    __shared__ float2 CH[4][NF], CW[4][NF];
    __shared__ float valsH[4][64], valsW[4][64];
    __shared__ float nred[4][2];
    int tid = threadIdx.x;
    int p = tid >> 6;
    int s = tid & 63;
    int pair = blockIdx.x * 4 + p;
    int i = pair >> 5, j = pair & 31;

    float nv = g_normp[i * 64 + s];
#pragma unroll
    for (int o = 16; o > 0; o >>= 1) nv += __shfl_down_sync(0xffffffffu, nv, o);
    if ((s & 31) == 0) nred[p][s >> 5] = nv;

    if (s < NF) {
        float xr = 0, xi = 0, yr = 0, yi = 0;
#pragma unroll
        for (int kc = 0; kc < NKC2; kc++) {
            float2 a = g_CpH[((kc * NF + s) * BS + i) * BS + j];
            float2 b = g_CpW[((kc * NF + s) * BS + i) * BS + j];
            xr += a.x; xi += a.y; yr += b.x; yi += b.y;
        }
        CH[p][s] = make_float2(xr, xi);
        CW[p][s] = make_float2(yr, yi);
    }
    __syncthreads();

    float sgn = (s & 1) ? -1.f : 1.f;
    float accH = CH[p][0].x + sgn * CH[p][32].x;
    float accW = CW[p][0].x + sgn * CW[p][32].x;
#pragma unroll
    for (int f = 1; f < 32; f++) {
        float x = (float)((f * s) & 63) / 32.0f;
        float sn, cs;
        sincospif(x, &sn, &cs);
        accH += 2.f * (CH[p][f].x * cs - CH[p][f].y * sn);
        accW += 2.f * (CW[p][f].x * cs - CW[p][f].y * sn);
    }
    valsH[p][s] = accH;
    valsW[p][s] = accW;
    __syncthreads();

    if (s == 0) {
        float best = valsH[p][0]; int bi = 0;
        for (int t = 1; t < 64; t++)
            if (valsH[p][t] > best) { best = valsH[p][t]; bi = t; }   // first max
        out_orien_f[i * 32 + j] = (float)bi;
        float nrm = sqrtf(nred[p][0] + nred[p][1] + 1e-8f);
        float q = valsW[p][bi] * (1.f / 64.f);
        float dot = q / nrm;
        out_dist[j * 32 + i] = 2.f - 2.f * dot;
    }
}

extern "C" void kernel_launch(void* const* d_in, const int* in_sizes, int n_in,
                              void* d_out, int out_size) {
    (void)in_sizes; (void)n_in; (void)out_size;
    const float* sat = (const float*)d_in[0];
    const float* grd = (const float*)d_in[1];
    float* out = (float*)d_out;

    k_dft3<<<4096, 256>>>(sat, grd, out);

    k_fgemm3<<<2 * NF * NKC, 256>>>();

    float* out_dist  = out + (size_t)2 * SATN;
    float* out_orien = out + (size_t)2 * SATN + 1024;
    k_inv<<<256, 256>>>(out_dist, out_orien);
}

// round 17
// speedup vs baseline: 1.5520x; 1.0006x over previous
#include <cuda_runtime.h>
#include <math.h>

#define BS 32
#define NF 33
#define KDIM 4096
#define SATN (32*64*64*64)
#define NKC 8            // k-chunk blocks per freq in fgemm
#define NKC2 32          // Cp partial slots (NKC * 4 k-subsets)

// -------- device scratch --------
__device__ float2 g_Sh[(size_t)NF * BS * KDIM];
__device__ float2 g_Gh[(size_t)NF * BS * KDIM];
__device__ float2 g_Sw[(size_t)NF * BS * KDIM];
__device__ float2 g_Gw[(size_t)NF * BS * KDIM];
__device__ float2 g_CpH[NKC2 * NF * BS * BS];
__device__ float2 g_CpW[NKC2 * NF * BS * BS];
__device__ float  g_normp[2048];

// cos(k*pi/32), k = 0..63. sin(k*pi/32) = TWC[(k+48)&63].
// All twiddle accesses use compile-time indices -> values fold into FFMA immediates.
__device__ constexpr float TWC[64] = {
     1.0f,
     0.9951847266721969f,  0.9807852804032304f,  0.9569403357322088f,
     0.9238795325112868f,  0.8819212643483551f,  0.8314696123025452f,
     0.7730104533627370f,  0.7071067811865476f,  0.6343932841636455f,
     0.5555702330196022f,  0.4713967368259976f,  0.3826834323650898f,
     0.2902846772544623f,  0.1950903220161283f,  0.0980171403295606f,
     0.0f,
    -0.0980171403295606f, -0.1950903220161283f, -0.2902846772544623f,
    -0.3826834323650898f, -0.4713967368259976f, -0.5555702330196022f,
    -0.6343932841636455f, -0.7071067811865476f, -0.7730104533627370f,
    -0.8314696123025452f, -0.8819212643483551f, -0.9238795325112868f,
    -0.9569403357322088f, -0.9807852804032304f, -0.9951847266721969f,
    -1.0f,
    -0.9951847266721969f, -0.9807852804032304f, -0.9569403357322088f,
    -0.9238795325112868f, -0.8819212643483551f, -0.8314696123025452f,
    -0.7730104533627370f, -0.7071067811865476f, -0.6343932841636455f,
    -0.5555702330196022f, -0.4713967368259976f, -0.3826834323650898f,
    -0.2902846772544623f, -0.1950903220161283f, -0.0980171403295606f,
     0.0f,
     0.0980171403295606f,  0.1950903220161283f,  0.2902846772544623f,
     0.3826834323650898f,  0.4713967368259976f,  0.5555702330196022f,
     0.6343932841636455f,  0.7071067811865476f,  0.7730104533627370f,
     0.8314696123025452f,  0.8819212643483551f,  0.9238795325112868f,
     0.9569403357322088f,  0.9807852804032304f,  0.9951847266721969f
};

// -------- DFT build: seo[n*65+col] = (e[n], o[n]); seo[32*65+col].x = e32 --------
__device__ __forceinline__ void dft_build(
    const float* slab, float2* seo, int axisH, int cc, int col, int m)
{
#pragma unroll
    for (int nn = 0; nn < 8; nn++) {
        int n = m + 4 * nn;
        float a, bb;
        if (axisH) {
            a  = slab[n * 65 + cc];
            bb = n ? slab[(64 - n) * 65 + cc] : 0.f;
        } else {
            a  = slab[cc * 65 + n];
            bb = n ? slab[cc * 65 + (64 - n)] : 0.f;
        }
        seo[n * 65 + col] = make_float2(a + bb, a - bb);
    }
    if (m == 0)
        seo[32 * 65 + col] =
            make_float2(axisH ? slab[32 * 65 + cc] : slab[cc * 65 + 32], 0.f);
}

// Compile-time-M DFT: thread handles f = M, M+4, ..., M+28 (+ f=32 for M=0).
template<int M>
__device__ __noinline__ void dft_compute_t(
    const float2* seo, float2* __restrict__ dst, int i, size_t off, int col)
{
    float e0  = seo[col].x;
    float e32 = seo[32 * 65 + col].x;
    float base = (M & 1) ? (e0 - e32) : (e0 + e32);

    float ar[8], ai[8];
#pragma unroll
    for (int u = 0; u < 8; u++) { ar[u] = base; ai[u] = 0.f; }

#pragma unroll
    for (int n = 1; n < 32; n++) {
        float2 eo = seo[n * 65 + col];
#pragma unroll
        for (int u = 0; u < 8; u++) {
            const int k = (((M + 4 * u) * n) & 63);        // compile-time
            ar[u] = fmaf(eo.x, TWC[k], ar[u]);
            ai[u] = fmaf(eo.y, TWC[(k + 48) & 63], ai[u]);
        }
    }
#pragma unroll
    for (int u = 0; u < 8; u++) {
        int f1 = M + 4 * u;
        dst[((size_t)f1 * BS + i) * KDIM + off] = make_float2(ar[u], -ai[u]);
    }
    if (M == 0) {                          // f = 32: cos = (-1)^n, sin = 0
        float arx = e0 + e32;
#pragma unroll
        for (int n = 1; n < 32; n++)
            arx = fmaf(seo[n * 65 + col].x, (n & 1) ? -1.f : 1.f, arx);
        dst[((size_t)32 * BS + i) * KDIM + off] = make_float2(arx, 0.f);
    }
}

__device__ __forceinline__ void dft_compute(
    const float2* seo, float2* __restrict__ dst, int i, size_t off, int col, int m)
{
    switch (m) {                           // warp-uniform branch
        case 0: dft_compute_t<0>(seo, dst, i, off, col); break;
        case 1: dft_compute_t<1>(seo, dst, i, off, col); break;
        case 2: dft_compute_t<2>(seo, dst, i, off, col); break;
        default: dft_compute_t<3>(seo, dst, i, off, col); break;
    }
}

// -------- merged DFT: sat+grd, H+W axes, passthrough copy, norm --------
__global__ void __launch_bounds__(256, 4)
k_dft3(const float* __restrict__ sat, const float* __restrict__ grd,
       float* __restrict__ out)
{
    __shared__ float slab[64 * 65];
    __shared__ __align__(16) float2 seo[33 * 65];
    __shared__ float red[8];

    int b = blockIdx.x;
    int tid = threadIdx.x;
    int is_grd = (b >= 2048);
    int b2 = is_grd ? (b - 2048) : b;
    const float* p = (is_grd ? grd : sat) + (size_t)b2 * 4096;
    float* op = out + (is_grd ? (size_t)SATN : 0) + (size_t)b2 * 4096;

    float nacc = 0.f;
#pragma unroll
    for (int t = 0; t < 16; t++) {
        int idx = tid + t * 256;
        float v = p[idx];
        slab[(idx >> 6) * 65 + (idx & 63)] = v;
        op[idx] = v;
        nacc = fmaf(v, v, nacc);
    }

    if (!is_grd) {
#pragma unroll
        for (int o = 16; o > 0; o >>= 1)
            nacc += __shfl_down_sync(0xffffffffu, nacc, o);
        if ((tid & 31) == 0) red[tid >> 5] = nacc;
    }
    __syncthreads();
    if (!is_grd && tid == 0) {
        float s = 0.f;
#pragma unroll
        for (int w = 0; w < 8; w++) s += red[w];
        g_normp[b2] = s;
    }

    int col = tid & 63;
    int m   = tid >> 6;
    int i = b2 >> 6, c = b2 & 63;
    size_t off = (size_t)c * 64 + col;

    {
        int cc = is_grd ? (63 - col) : col;
        dft_build(slab, seo, 1, cc, col, m);
        __syncthreads();
        dft_compute(seo, is_grd ? g_Gh : g_Sh, i, off, col, m);
    }
    __syncthreads();
    {
        dft_build(slab, seo, 0, col, col, m);
        __syncthreads();
        dft_compute(seo, is_grd ? g_Gw : g_Sw, i, off, col, m);
    }
}

// -------- per-frequency complex GEMM, 3-mult (Karatsuba) MACs, 4x4 tiles --------
#define FST 36
__global__ void __launch_bounds__(256, 2) k_fgemm3() {
    __shared__ __align__(16) float sSr[32 * FST];
    __shared__ __align__(16) float sSi[32 * FST];
    __shared__ __align__(16) float sSp[32 * FST];
    __shared__ __align__(16) float sG1[32 * FST];
    __shared__ __align__(16) float sG2[32 * FST];
    __shared__ __align__(16) float sG3[32 * FST];

    int bid = blockIdx.x;
    int sel = (bid >= NF * NKC);
    if (sel) bid -= NF * NKC;
    int f  = bid >> 3;
    int kc = bid & 7;

    const float2* S = sel ? g_Sw : g_Sh;
    const float2* G = sel ? g_Gw : g_Gh;
    float2* Cp      = sel ? g_CpW : g_CpH;

    int tid = threadIdx.x;
    int li = tid >> 3;
    int ls = tid & 7;
    int t    = tid & 63;
    int ksub = tid >> 6;
    int i0 = (t >> 3) * 4;
    int j0 = (t & 7) * 4;

    const float2* Sb = S + (size_t)f * BS * KDIM + kc * 512;
    const float2* Gb = G + (size_t)f * BS * KDIM + kc * 512;
    const float4* Sg4 = (const float4*)(Sb + (size_t)li * KDIM);
    const float4* Gg4 = (const float4*)(Gb + (size_t)li * KDIM);

    float K1[4][4], K2[4][4], K3[4][4];
#pragma unroll
    for (int di = 0; di < 4; di++)
#pragma unroll
        for (int dj = 0; dj < 4; dj++) { K1[di][dj] = 0.f; K2[di][dj] = 0.f; K3[di][dj] = 0.f; }

    for (int kt = 0; kt < 16; kt++) {
        __syncthreads();
#pragma unroll
        for (int u = 0; u < 2; u++) {
            int k4 = ls + u * 8;
            float4 s = Sg4[kt * 16 + k4];
            float4 g = Gg4[kt * 16 + k4];
            int r0 = (2 * k4) * FST + li, r1 = (2 * k4 + 1) * FST + li;
            sSr[r0] = s.x;  sSi[r0] = s.y;  sSp[r0] = s.x + s.y;
            sSr[r1] = s.z;  sSi[r1] = s.w;  sSp[r1] = s.z + s.w;
            sG1[r0] = g.x;  sG2[r0] = -g.y - g.x;  sG3[r0] = g.x - g.y;
            sG1[r1] = g.z;  sG2[r1] = -g.w - g.z;  sG3[r1] = g.z - g.w;
        }
        __syncthreads();
#pragma unroll
        for (int kk = 0; kk < 8; kk++) {
            int k = ksub * 8 + kk;
            float4 var = *(const float4*)&sSr[k * FST + i0];
            float4 vai = *(const float4*)&sSi[k * FST + i0];
            float4 vap = *(const float4*)&sSp[k * FST + i0];
            float4 vg1 = *(const float4*)&sG1[k * FST + j0];
            float4 vg2 = *(const float4*)&sG2[k * FST + j0];
            float4 vg3 = *(const float4*)&sG3[k * FST + j0];
            const float* par = (const float*)&var;
            const float* pai = (const float*)&vai;
            const float* pap = (const float*)&vap;
            const float* pg1 = (const float*)&vg1;
            const float* pg2 = (const float*)&vg2;
            const float* pg3 = (const float*)&vg3;
#pragma unroll
            for (int di = 0; di < 4; di++) {
#pragma unroll
                for (int dj = 0; dj < 4; dj++) {
                    K1[di][dj] = fmaf(pg1[dj], pap[di], K1[di][dj]);
                    K2[di][dj] = fmaf(pg2[dj], par[di], K2[di][dj]);
                    K3[di][dj] = fmaf(pg3[dj], pai[di], K3[di][dj]);
                }
            }
        }
    }
    int kc2 = kc * 4 + ksub;
    float2* outp = Cp + ((size_t)kc2 * NF + f) * BS * BS;
#pragma unroll
    for (int di = 0; di < 4; di++)
#pragma unroll
        for (int dj = 0; dj < 4; dj++)
            outp[(i0 + di) * 32 + (j0 + dj)] =
                make_float2(K1[di][dj] - K3[di][dj], K1[di][dj] + K2[di][dj]);
}

// -------- fused inverse transform + norm + first-max argmax + distance --------
__global__ void k_inv(float* __restrict__ out_dist, float* __restrict__ out_orien_f) {
    __shared__ float2 CH[4][NF], CW[4][NF];
    __shared__ float valsH[4][64], valsW[4][64];
    __shared__ float nred[4][2];
    int tid = threadIdx.x;
    int p = tid >> 6;
    int s = tid & 63;
    int pair = blockIdx.x * 4 + p;
    int i = pair >> 5, j = pair & 31;

    float nv = g_normp[i * 64 + s];
#pragma unroll
    for (int o = 16; o > 0; o >>= 1) nv += __shfl_down_sync(0xffffffffu, nv, o);
    if ((s & 31) == 0) nred[p][s >> 5] = nv;

    if (s < NF) {
        float xr = 0, xi = 0, yr = 0, yi = 0;
#pragma unroll
        for (int kc = 0; kc < NKC2; kc++) {
            float2 a = g_CpH[((kc * NF + s) * BS + i) * BS + j];
            float2 b = g_CpW[((kc * NF + s) * BS + i) * BS + j];
            xr += a.x; xi += a.y; yr += b.x; yi += b.y;
        }
        CH[p][s] = make_float2(xr, xi);
        CW[p][s] = make_float2(yr, yi);
    }
    __syncthreads();

    float sgn = (s & 1) ? -1.f : 1.f;
    float accH = CH[p][0].x + sgn * CH[p][32].x;
    float accW = CW[p][0].x + sgn * CW[p][32].x;
#pragma unroll
    for (int f = 1; f < 32; f++) {
        float x = (float)((f * s) & 63) / 32.0f;
        float sn, cs;
        sincospif(x, &sn, &cs);
        accH += 2.f * (CH[p][f].x * cs - CH[p][f].y * sn);
        accW += 2.f * (CW[p][f].x * cs - CW[p][f].y * sn);
    }
    valsH[p][s] = accH;
    valsW[p][s] = accW;
    __syncthreads();

    if (s == 0) {
        float best = valsH[p][0]; int bi = 0;
        for (int t = 1; t < 64; t++)
            if (valsH[p][t] > best) { best = valsH[p][t]; bi = t; }   // first max
        out_orien_f[i * 32 + j] = (float)bi;
        float nrm = sqrtf(nred[p][0] + nred[p][1] + 1e-8f);
        float q = valsW[p][bi] * (1.f / 64.f);
        float dot = q / nrm;
        out_dist[j * 32 + i] = 2.f - 2.f * dot;
    }
}

extern "C" void kernel_launch(void* const* d_in, const int* in_sizes, int n_in,
                              void* d_out, int out_size) {
    (void)in_sizes; (void)n_in; (void)out_size;
    const float* sat = (const float*)d_in[0];
    const float* grd = (const float*)d_in[1];
    float* out = (float*)d_out;

    k_dft3<<<4096, 256>>>(sat, grd, out);

    k_fgemm3<<<2 * NF * NKC, 256>>>();

    float* out_dist  = out + (size_t)2 * SATN;
    float* out_orien = out + (size_t)2 * SATN + 1024;
    k_inv<<<256, 256>>>(out_dist, out_orien);
}